// round 12
// baseline (speedup 1.0000x reference)
#include <cuda_runtime.h>
#include <math.h>
#include <stdint.h>

#define NN 32
#define CC 32
#define MM 10
#define SSZ 196
#define CPB 8                 // channels per CTA
#define ITEMS (CPB*SSZ)       // 1568 items per CTA
#define NQUADS (ITEMS/4)      // 392 item-quads per CTA
#define THREADS 384
#define QITER 2               // ceil(392/384)
#define BBF 6272.0f
#define EPSF 1e-6f
#define LAM_INIT 0.001f
#define LAM_ROUT 0.001f
#define LN2PI 1.8378770664093453f

typedef unsigned long long u64;

// ---- packed f32x2 helpers ----
__device__ __forceinline__ u64 pk2(float lo, float hi) {
    u64 r; asm("mov.b64 %0, {%1,%2};" : "=l"(r) : "f"(lo), "f"(hi)); return r;
}
__device__ __forceinline__ u64 bc2(float x) { return pk2(x, x); }
__device__ __forceinline__ void upk(u64 v, float& lo, float& hi) {
    asm("mov.b64 {%0,%1}, %2;" : "=f"(lo), "=f"(hi) : "l"(v));
}
__device__ __forceinline__ u64 fma2(u64 a, u64 b, u64 c) {
    u64 d; asm("fma.rn.f32x2 %0, %1, %2, %3;" : "=l"(d) : "l"(a), "l"(b), "l"(c)); return d;
}
__device__ __forceinline__ u64 mul2(u64 a, u64 b) {
    u64 d; asm("mul.rn.f32x2 %0, %1, %2;" : "=l"(d) : "l"(a), "l"(b)); return d;
}
__device__ __forceinline__ u64 add2(u64 a, u64 b) {
    u64 d; asm("add.rn.f32x2 %0, %1, %2;" : "=l"(d) : "l"(a), "l"(b)); return d;
}
__device__ __forceinline__ u64 shx2(u64 v, int d) {
    return __shfl_xor_sync(0xffffffffu, v, d);
}

// ---- cluster helpers ----
__device__ __forceinline__ void cluster_sync_() {
    asm volatile("barrier.cluster.arrive.aligned;" ::: "memory");
    asm volatile("barrier.cluster.wait.aligned;"   ::: "memory");
}
__device__ __forceinline__ uint32_t smem_u32(const void* p) {
    uint32_t a;
    asm("{ .reg .u64 t; cvta.to.shared.u64 t, %1; cvt.u32.u64 %0, t; }" : "=r"(a) : "l"(p));
    return a;
}
__device__ __forceinline__ float cluster_ld_f32(uint32_t laddr, uint32_t rank) {
    uint32_t ra; float v;
    asm("mapa.shared::cluster.u32 %0, %1, %2;" : "=r"(ra) : "r"(laddr), "r"(rank));
    asm volatile("ld.shared::cluster.f32 %0, [%1];" : "=f"(v) : "r"(ra) : "memory");
    return v;
}

__device__ __forceinline__ int bitrev4(int x) {
    return ((x&1)<<3) | (((x>>1)&1)<<2) | (((x>>2)&1)<<1) | ((x>>3)&1);
}

// SEL-free permuted dual reduction with merged tail (see R11).
// Lane L placed slot (L&7)^bitrev3(j) at position j for both arrays.
// Returns the single scalar this lane owns: array = bit3, slot = lane&7,
// component (lo/hi) = bit4.
__device__ __forceinline__ float reduce8x2r(u64 (&yA)[8], u64 (&yB)[8], int lane)
{
#pragma unroll
    for (int j = 0; j < 4; j++) {
        yA[j] = add2(yA[j], shx2(yA[j+4], 1));
        yB[j] = add2(yB[j], shx2(yB[j+4], 1));
    }
#pragma unroll
    for (int j = 0; j < 2; j++) {
        yA[j] = add2(yA[j], shx2(yA[j+2], 2));
        yB[j] = add2(yB[j], shx2(yB[j+2], 2));
    }
    yA[0] = add2(yA[0], shx2(yA[1], 4));
    yB[0] = add2(yB[0], shx2(yB[1], 4));
    u64 keep = (lane & 8) ? yB[0] : yA[0];
    u64 send = (lane & 8) ? yA[0] : yB[0];
    u64 z = add2(keep, shx2(send, 8));
    float lo, hi; upk(z, lo, hi);
    float kp = (lane & 16) ? hi : lo;
    float sd = (lane & 16) ? lo : hi;
    return kp + __shfl_xor_sync(0xffffffffu, sd, 16);
}

// 16 scalars across 32 lanes (R); lane owns bitrev4(lane&15).
__device__ __forceinline__ float reduce16_to_lane(float (&y)[16], int lane)
{
#pragma unroll
    for (int j = 0; j < 8; j++) {
        bool up = lane & 1;
        float s = up ? y[j] : y[j+8];
        float k = up ? y[j+8] : y[j];
        y[j] = k + __shfl_xor_sync(0xffffffffu, s, 1);
    }
#pragma unroll
    for (int j = 0; j < 4; j++) {
        bool up = lane & 2;
        float s = up ? y[j] : y[j+4];
        float k = up ? y[j+4] : y[j];
        y[j] = k + __shfl_xor_sync(0xffffffffu, s, 2);
    }
#pragma unroll
    for (int j = 0; j < 2; j++) {
        bool up = lane & 4;
        float s = up ? y[j] : y[j+2];
        float k = up ? y[j+2] : y[j];
        y[j] = k + __shfl_xor_sync(0xffffffffu, s, 4);
    }
    {
        bool up = lane & 8;
        float s = up ? y[0] : y[1];
        float k = up ? y[1] : y[0];
        y[0] = k + __shfl_xor_sync(0xffffffffu, s, 8);
    }
    y[0] += __shfl_xor_sync(0xffffffffu, y[0], 16);
    return y[0];
}

#define CJ(j)  ((((j)&1)<<1) | (((j)>>1)&1))
#define BR3(j) (((((j)&1))<<2) | ((j)&2) | (((j)>>2)&1))

// V chain for one item component (x of each float4 etc.) — macro-free inline
#define VCHAIN(comp) \
    fma2(bc2(lf[4*cj].comp),   wc[0], \
    fma2(bc2(lf[4*cj+1].comp), wc[1], \
    fma2(bc2(lf[4*cj+2].comp), wc[2], \
    mul2(bc2(lf[4*cj+3].comp), wc[3]))))

// ======================= the single fused kernel =======================
__global__ __cluster_dims__(4,1,1) __launch_bounds__(THREADS,1)
void k_mega(const float* __restrict__ l, const float* __restrict__ g,
            const float* __restrict__ w, const float* __restrict__ beta_a,
            const float* __restrict__ beta_u, float* __restrict__ out)
{
    __shared__ alignas(16) float w_sh[CPB*160];
    __shared__ alignas(16) float ep_sh[MM*32];   // [m][u][i2lo,i2hi,mu2nlo,mu2nhi]
    __shared__ alignas(16) float Ush[CPB*64];    // per-channel l-statistics (pass A)
    __shared__ float K_sh[10], a_sh[10], Rtot[10];
    __shared__ float acc1[160], acc2[160], accR[16];

    const int tid = threadIdx.x, lane = tid & 31;
    const int crank = blockIdx.x & 3;
    const int n     = blockIdx.x >> 2;

    const int Lp = (lane >> 1) & 3;
    const int L0 = lane & 1;
    const int L7 = lane & 7;

    for (int i = tid; i < CPB*160; i += THREADS)
        w_sh[i] = w[(crank*CPB)*160 + i];
    for (int i = tid; i < CPB*64; i += THREADS)
        Ush[i] = 0.f;
    if (tid < 160) { acc1[tid] = 0.f; acc2[tid] = 0.f; }
    if (tid < 16)  accR[tid] = 0.f;
    __syncthreads();

    float* accp = (((lane>>3)&1) ? acc2 : acc1) + 4*Lp + 2*L0 + ((lane>>4)&1);

    const uint32_t a1addr = smem_u32(&acc1[tid < 160 ? tid : 0]);
    const uint32_t a2addr = smem_u32(&acc2[tid < 160 ? tid : 0]);
    const uint32_t aRaddr = smem_u32(&accR[tid < 16  ? tid : 0]);

    const int em = (tid < 160) ? (tid >> 4) : 0;
    const int ed = tid & 15;
    const float ba = beta_a[em], bu = beta_u[em];

    // ================= PASS A via per-channel l-statistics =================
    // 32 work units over 12 warps: wi = k*12 + warp, skip wi>=32 (warp-uniform).
    for (int k = 0; k < 3; k++) {
        const int wi = k*12 + (tid >> 5);
        if (wi < 32) {
            const int cl = wi >> 2, sub = wi & 3;
            const int pi = sub*32 + lane;        // pair index within channel
            const bool act = pi < (SSZ/2);
            const int s = act ? 2*pi : 0;
            const float* lbase = l + ((size_t)(n*CC + crank*CPB + cl)*16)*SSZ + s;
            float2 lf[16];
#pragma unroll
            for (int i = 0; i < 16; i++) {
                int d = 4*((i>>2) ^ Lp) + ((i&2) ^ (L0<<1)) + (i&1);
                float2 t = *(const float2*)(lbase + d*SSZ);
                lf[i] = act ? t : make_float2(0.f, 0.f);
            }
            float U1s[16], sq[16];
#pragma unroll
            for (int i = 0; i < 16; i++) {
                U1s[i] = lf[i].x + lf[i].y;
                sq[i]  = fmaf(lf[i].x, lf[i].x, lf[i].y*lf[i].y);
            }
            float p01r[4], p23r[4], p02v[4], p13v[4], p03r[4], p12r[4];
#pragma unroll
            for (int gg = 0; gg < 4; gg++) {
                const float2* b = lf + 4*gg;
                p01r[gg] = fmaf(b[0].x, b[1].x, b[0].y*b[1].y);
                p23r[gg] = fmaf(b[2].x, b[3].x, b[2].y*b[3].y);
                p02v[gg] = fmaf(b[0].x, b[2].x, b[0].y*b[2].y);
                p13v[gg] = fmaf(b[1].x, b[3].x, b[1].y*b[3].y);
                p03r[gg] = fmaf(b[0].x, b[3].x, b[0].y*b[3].y);
                p12r[gg] = fmaf(b[1].x, b[2].x, b[1].y*b[2].y);
            }
            u64 y1[8], y1b[8], y2[8], y2b[8];
#pragma unroll
            for (int j = 0; j < 8; j++) {
                const int gg = CJ(j), jj = j >> 2;
                y1 [j] = pk2(U1s[4*gg+2*jj], U1s[4*gg+2*jj+1]);
                y1b[j] = pk2(sq [4*gg+2*jj], sq [4*gg+2*jj+1]);
                u64 k0  = L0 ? pk2(p23r[gg], p01r[gg]) : pk2(p01r[gg], p23r[gg]);
                u64 k1  = pk2(p02v[gg], p13v[gg]);
                u64 k0b = L0 ? pk2(p12r[gg], p03r[gg]) : pk2(p03r[gg], p12r[gg]);
                const int kb = L0 ^ jj;
                y2 [j] = kb ? k1   : k0;
                y2b[j] = kb ? 0ull : k0b;
            }
            const int sidx = ((lane>>3)&1)*16 + 2*(lane&7) + ((lane>>4)&1);
            float r1 = reduce8x2r(y1, y1b, lane);
            atomicAdd(&Ush[cl*64 + sidx], r1);
            float r2 = reduce8x2r(y2, y2b, lane);
            atomicAdd(&Ush[cl*64 + 32 + sidx], r2);
        }
    }
    __syncthreads();

    // ----- contraction: S1/S2 partials for this CTA's 8 channels -----
    if (tid < 160) {
        const int p_ = ed >> 2, r_ = ed & 3;
        float s1 = 0.f, s2 = 0.f;
#pragma unroll
        for (int c = 0; c < CPB; c++) {
            const float* u   = &Ush[c*64];
            const float* wcm = &w_sh[c*160 + em*16];
            float w0 = wcm[r_], w1 = wcm[4+r_], w2 = wcm[8+r_], w3 = wcm[12+r_];
            const float* u1 = u + 4*p_;
            s1 += w0*u1[0] + w1*u1[1] + w2*u1[2] + w3*u1[3];
            const float* dq = u + 16 + 4*p_;
            s2 += w0*w0*dq[0] + w1*w1*dq[1] + w2*w2*dq[2] + w3*w3*dq[3];
            const float* pp = u + 32 + 4*p_;
            float cr = w0*w1*pp[0] + w2*w3*pp[1] + w0*w2*pp[2] + w1*w3*pp[3];
            const float* pv = u + 48 + 4*p_;
            cr += w0*w3*pv[0] + w1*w2*pv[1];
            s2 += 2.f*cr;
        }
        acc1[tid] = s1;
        acc2[tid] = s2;
    }
    __syncthreads();
    cluster_sync_();

    // ----- combine S1/S2 across the 4 CTAs -----
    float S1 = 0.f, S2 = 0.f;
    if (tid < 160) {
#pragma unroll
        for (uint32_t rk = 0; rk < 4; rk++) {
            S1 += cluster_ld_f32(a1addr, rk);
            S2 += cluster_ld_f32(a2addr, rk);
        }
    }
    cluster_sync_();
    if (tid < 160) { acc1[tid] = 0.f; acc2[tid] = 0.f; }

    // ----- epilogue A -----
    if (tid < 160) {
        float gv = g[(n*MM + em)*16 + ed];
        float sig0 = S2 - 2.f*gv*S1 + BBF*gv*gv + EPSF;
        float sl = logf(sig0);
#pragma unroll
        for (int o = 8; o > 0; o >>= 1) sl += __shfl_xor_sync(0xffffffffu, sl, o);

        float a0 = 1.f / (1.f + expf(-(LAM_INIT * (ba - 16.f*bu - 0.5f*sl))));
        float rsum  = BBF * a0 * 0.1f;
        float coeff = (a0 * 0.1f) / (rsum + EPSF);
        float mu    = coeff * S1;
        float sig   = coeff * (S2 - 2.f*mu*S1 + BBF*mu*mu) + EPSF;
        float sl2 = logf(sig);
#pragma unroll
        for (int o = 8; o > 0; o >>= 1) sl2 += __shfl_xor_sync(0xffffffffu, sl2, o);

        float logit = LAM_ROUT * (ba - rsum * (16.f*bu + 0.5f*sl2));
        float a1 = 1.f / (1.f + expf(-logit));

        float i2  = 0.5f / sig;
        float cst = mu*mu*i2;
#pragma unroll
        for (int o = 8; o > 0; o >>= 1) cst += __shfl_xor_sync(0xffffffffu, cst, o);

        ep_sh[em*32 + (ed>>1)*4 +     (ed&1)] = i2;
        ep_sh[em*32 + (ed>>1)*4 + 2 + (ed&1)] = -(mu / sig);
        if (ed == 0) {
            a_sh[em] = a1;
            K_sh[em] = -0.5f*sl2 - 8.f*LN2PI + logf(a1) - cst;
        }
    }
    __syncthreads();

    // ================= routing iterations 1 and 2 =================
    for (int it = 0; it < 2; it++) {
#pragma unroll
        for (int k = 0; k < QITER; k++) {
            // warp-uniform skip of fully-inactive warps (no barriers inside body)
            if ((tid & ~31) + k*THREADS >= NQUADS) continue;
            const int qu = tid + k*THREADS;
            const bool act = qu < NQUADS;
            const int quc = act ? qu : 0;
            const int cl = quc / (SSZ/4), s = 4*(quc - cl*(SSZ/4));
            const float* lbase = l + ((size_t)(n*CC + crank*CPB + cl)*16)*SSZ + s;
            float4 lf[16];
#pragma unroll
            for (int i = 0; i < 16; i++) {
                int d = 4*((i>>2) ^ Lp) + (i&3);
                float4 t = *(const float4*)(lbase + d*SSZ);
                lf[i] = act ? t : make_float4(0.f, 0.f, 0.f, 0.f);
            }

            // ---- E-step: 4 items ----
            float lnapA[10], lnapB[10], lnapC[10], lnapD[10];
#pragma unroll
            for (int m = 0; m < MM; m++) {
                const float* wm = &w_sh[cl*160 + m*16];
                u64 wA[4], wB[4];
#pragma unroll
                for (int q = 0; q < 4; q++) {
                    wA[q] = *(const u64*)(wm + 4*q + 2*L0);
                    wB[q] = *(const u64*)(wm + 4*q + 2*(L0^1));
                }
                u64 qA = 0ull, qB = 0ull, qC = 0ull, qD = 0ull;
#pragma unroll
                for (int j = 0; j < 8; j++) {
                    const int cj = CJ(j);
                    const u64* wc = (j < 4) ? wA : wB;
                    const int u = L7 ^ BR3(j);
                    ulonglong2 ep = *(const ulonglong2*)&ep_sh[m*32 + u*4];
                    u64 vA = VCHAIN(x);
                    u64 vB = VCHAIN(y);
                    u64 vC = VCHAIN(z);
                    u64 vD = VCHAIN(w);
                    qA = fma2(vA, fma2(vA, ep.x, ep.y), qA);
                    qB = fma2(vB, fma2(vB, ep.x, ep.y), qB);
                    qC = fma2(vC, fma2(vC, ep.x, ep.y), qC);
                    qD = fma2(vD, fma2(vD, ep.x, ep.y), qD);
                }
                float ql, qh;
                upk(qA, ql, qh); lnapA[m] = K_sh[m] - (ql + qh);
                upk(qB, ql, qh); lnapB[m] = K_sh[m] - (ql + qh);
                upk(qC, ql, qh); lnapC[m] = K_sh[m] - (ql + qh);
                upk(qD, ql, qh); lnapD[m] = K_sh[m] - (ql + qh);
            }

            // stable softmax * a, 4 items; inactive threads masked to 0
            {
                float mxA = lnapA[0], mxB = lnapB[0], mxC = lnapC[0], mxD = lnapD[0];
#pragma unroll
                for (int m = 1; m < MM; m++) {
                    mxA = fmaxf(mxA, lnapA[m]); mxB = fmaxf(mxB, lnapB[m]);
                    mxC = fmaxf(mxC, lnapC[m]); mxD = fmaxf(mxD, lnapD[m]);
                }
                float dA = 0.f, dB = 0.f, dC = 0.f, dD = 0.f;
#pragma unroll
                for (int m = 0; m < MM; m++) {
                    lnapA[m] = __expf(lnapA[m] - mxA); dA += lnapA[m];
                    lnapB[m] = __expf(lnapB[m] - mxB); dB += lnapB[m];
                    lnapC[m] = __expf(lnapC[m] - mxC); dC += lnapC[m];
                    lnapD[m] = __expf(lnapD[m] - mxD); dD += lnapD[m];
                }
                float sA = act ? (1.f / dA) : 0.f;
                float sB = act ? (1.f / dB) : 0.f;
                float sC = act ? (1.f / dC) : 0.f;
                float sD = act ? (1.f / dD) : 0.f;
#pragma unroll
                for (int m = 0; m < MM; m++) {
                    lnapA[m] = lnapA[m] * sA * a_sh[m];
                    lnapB[m] = lnapB[m] * sB * a_sh[m];
                    lnapC[m] = lnapC[m] * sC * a_sh[m];
                    lnapD[m] = lnapD[m] * sD * a_sh[m];
                }
            }

            // ---- M-step statistics: quad-accumulated before reduction ----
#pragma unroll
            for (int m = 0; m < MM; m++) {
                const float* wm = &w_sh[cl*160 + m*16];
                u64 wA[4], wB[4];
#pragma unroll
                for (int q = 0; q < 4; q++) {
                    wA[q] = *(const u64*)(wm + 4*q + 2*L0);
                    wB[q] = *(const u64*)(wm + 4*q + 2*(L0^1));
                }
                u64 rA = bc2(lnapA[m]), rB = bc2(lnapB[m]);
                u64 rC = bc2(lnapC[m]), rD = bc2(lnapD[m]);
                u64 yV[8], yV2[8];
#pragma unroll
                for (int j = 0; j < 8; j++) {
                    const int cj = CJ(j);
                    const u64* wc = (j < 4) ? wA : wB;
                    u64 vA = VCHAIN(x);
                    u64 vB = VCHAIN(y);
                    u64 vC = VCHAIN(z);
                    u64 vD = VCHAIN(w);
                    u64 cA = mul2(rA, vA), cB = mul2(rB, vB);
                    u64 cC = mul2(rC, vC), cD = mul2(rD, vD);
                    yV [j] = add2(add2(cA, cB), add2(cC, cD));
                    yV2[j] = add2(add2(mul2(cA, vA), mul2(cB, vB)),
                                  add2(mul2(cC, vC), mul2(cD, vD)));
                }
                float res = reduce8x2r(yV, yV2, lane);
                atomicAdd(accp + m*16, res);
            }
            // R sums (quad-summed)
            {
                float y[16];
#pragma unroll
                for (int m = 0; m < MM; m++)
                    y[m] = (lnapA[m] + lnapB[m]) + (lnapC[m] + lnapD[m]);
#pragma unroll
                for (int m = MM; m < 16; m++) y[m] = 0.f;
                float val = reduce16_to_lane(y, lane);
                int idx4 = bitrev4(lane & 15);
                if (lane < 16 && idx4 < MM) atomicAdd(&accR[idx4], val);
            }
        }
        __syncthreads();
        cluster_sync_();

        // combine A1/A2/R across CTAs
        float A1 = 0.f, A2 = 0.f, R = 0.f;
        if (tid < 160) {
#pragma unroll
            for (uint32_t rk = 0; rk < 4; rk++) {
                A1 += cluster_ld_f32(a1addr, rk);
                A2 += cluster_ld_f32(a2addr, rk);
            }
        }
        if (tid < 16) {
#pragma unroll
            for (uint32_t rk = 0; rk < 4; rk++) R += cluster_ld_f32(aRaddr, rk);
        }
        cluster_sync_();
        if (tid < 160) { acc1[tid] = 0.f; acc2[tid] = 0.f; }
        if (tid < 16)  accR[tid] = 0.f;
        if (tid < 10)  Rtot[tid] = R;
        __syncthreads();

        if (tid < 160) {
            float Rm  = Rtot[em];
            float inv = 1.f / (Rm + EPSF);
            float mu  = A1 * inv;
            float sig = (A2 - 2.f*mu*A1 + mu*mu*Rm) * inv + EPSF;
            float sl  = logf(sig);
#pragma unroll
            for (int o = 8; o > 0; o >>= 1) sl += __shfl_xor_sync(0xffffffffu, sl, o);

            float logit = LAM_ROUT * (ba - Rm * (16.f*bu + 0.5f*sl));
            float a = 1.f / (1.f + expf(-logit));

            if (it == 0) {
                float i2  = 0.5f / sig;
                float cst = mu*mu*i2;
#pragma unroll
                for (int o = 8; o > 0; o >>= 1) cst += __shfl_xor_sync(0xffffffffu, cst, o);
                ep_sh[em*32 + (ed>>1)*4 +     (ed&1)] = i2;
                ep_sh[em*32 + (ed>>1)*4 + 2 + (ed&1)] = -(mu / sig);
                if (ed == 0) {
                    a_sh[em] = a;
                    K_sh[em] = -0.5f*sl - 8.f*LN2PI + logf(a) - cst;
                }
            } else if (crank == 0) {
                out[NN*MM + n*160 + tid] = mu;          // mu block (N, M, 16)
                if (ed == 0) out[n*MM + em] = a;        // a_out block (N, M)
            }
        }
        __syncthreads();
    }
}

extern "C" void kernel_launch(void* const* d_in, const int* in_sizes, int n_in,
                              void* d_out, int out_size)
{
    const float* l      = (const float*)d_in[0];
    const float* g      = (const float*)d_in[1];
    const float* weight = (const float*)d_in[2];
    const float* beta_a = (const float*)d_in[3];
    const float* beta_u = (const float*)d_in[4];
    float* out = (float*)d_out;

    k_mega<<<NN*4, THREADS>>>(l, g, weight, beta_a, beta_u, out);

    (void)in_sizes; (void)n_in; (void)out_size;
}

// round 13
// speedup vs baseline: 1.4051x; 1.4051x over previous
#include <cuda_runtime.h>
#include <math.h>
#include <stdint.h>

#define NN 32
#define CC 32
#define MM 10
#define SSZ 196
#define CPB 8                 // channels per CTA
#define ITEMS (CPB*SSZ)       // 1568 items per CTA
#define NPAIRS (ITEMS/2)      // 784 item-pairs per CTA
#define THREADS 512
#define NITER ((NPAIRS + THREADS - 1) / THREADS)   // 2, uniform for all threads
#define BBF 6272.0f
#define EPSF 1e-6f
#define LAM_INIT 0.001f
#define LAM_ROUT 0.001f
#define LN2PI 1.8378770664093453f

typedef unsigned long long u64;

// ---- packed f32x2 helpers ----
__device__ __forceinline__ u64 pk2(float lo, float hi) {
    u64 r; asm("mov.b64 %0, {%1,%2};" : "=l"(r) : "f"(lo), "f"(hi)); return r;
}
__device__ __forceinline__ u64 bc2(float x) { return pk2(x, x); }
__device__ __forceinline__ void upk(u64 v, float& lo, float& hi) {
    asm("mov.b64 {%0,%1}, %2;" : "=f"(lo), "=f"(hi) : "l"(v));
}
__device__ __forceinline__ u64 fma2(u64 a, u64 b, u64 c) {
    u64 d; asm("fma.rn.f32x2 %0, %1, %2, %3;" : "=l"(d) : "l"(a), "l"(b), "l"(c)); return d;
}
__device__ __forceinline__ u64 mul2(u64 a, u64 b) {
    u64 d; asm("mul.rn.f32x2 %0, %1, %2;" : "=l"(d) : "l"(a), "l"(b)); return d;
}
__device__ __forceinline__ u64 add2(u64 a, u64 b) {
    u64 d; asm("add.rn.f32x2 %0, %1, %2;" : "=l"(d) : "l"(a), "l"(b)); return d;
}
__device__ __forceinline__ u64 shx2(u64 v, int d) {
    return __shfl_xor_sync(0xffffffffu, v, d);
}

// ---- cluster helpers ----
__device__ __forceinline__ void cluster_sync_() {
    asm volatile("barrier.cluster.arrive.aligned;" ::: "memory");
    asm volatile("barrier.cluster.wait.aligned;"   ::: "memory");
}
__device__ __forceinline__ uint32_t smem_u32(const void* p) {
    uint32_t a;
    asm("{ .reg .u64 t; cvta.to.shared.u64 t, %1; cvt.u32.u64 %0, t; }" : "=r"(a) : "l"(p));
    return a;
}
__device__ __forceinline__ float cluster_ld_f32(uint32_t laddr, uint32_t rank) {
    uint32_t ra; float v;
    asm("mapa.shared::cluster.u32 %0, %1, %2;" : "=r"(ra) : "r"(laddr), "r"(rank));
    asm volatile("ld.shared::cluster.f32 %0, [%1];" : "=f"(v) : "r"(ra) : "memory");
    return v;
}

__device__ __forceinline__ int bitrev4(int x) {
    return ((x&1)<<3) | (((x>>1)&1)<<2) | (((x>>2)&1)<<1) | ((x>>3)&1);
}

// SEL-free permuted dual reduction with merged tail (see R11).
// Lane L placed slot (L&7)^bitrev3(j) at position j for both arrays.
// Returns the single scalar this lane owns: array = bit3, slot = lane&7,
// component (lo/hi) = bit4.
__device__ __forceinline__ float reduce8x2r(u64 (&yA)[8], u64 (&yB)[8], int lane)
{
#pragma unroll
    for (int j = 0; j < 4; j++) {
        yA[j] = add2(yA[j], shx2(yA[j+4], 1));
        yB[j] = add2(yB[j], shx2(yB[j+4], 1));
    }
#pragma unroll
    for (int j = 0; j < 2; j++) {
        yA[j] = add2(yA[j], shx2(yA[j+2], 2));
        yB[j] = add2(yB[j], shx2(yB[j+2], 2));
    }
    yA[0] = add2(yA[0], shx2(yA[1], 4));
    yB[0] = add2(yB[0], shx2(yB[1], 4));
    u64 keep = (lane & 8) ? yB[0] : yA[0];
    u64 send = (lane & 8) ? yA[0] : yB[0];
    u64 z = add2(keep, shx2(send, 8));
    float lo, hi; upk(z, lo, hi);
    float kp = (lane & 16) ? hi : lo;
    float sd = (lane & 16) ? lo : hi;
    return kp + __shfl_xor_sync(0xffffffffu, sd, 16);
}

// 16 scalars across 32 lanes (R); lane owns bitrev4(lane&15).
__device__ __forceinline__ float reduce16_to_lane(float (&y)[16], int lane)
{
#pragma unroll
    for (int j = 0; j < 8; j++) {
        bool up = lane & 1;
        float s = up ? y[j] : y[j+8];
        float k = up ? y[j+8] : y[j];
        y[j] = k + __shfl_xor_sync(0xffffffffu, s, 1);
    }
#pragma unroll
    for (int j = 0; j < 4; j++) {
        bool up = lane & 2;
        float s = up ? y[j] : y[j+4];
        float k = up ? y[j+4] : y[j];
        y[j] = k + __shfl_xor_sync(0xffffffffu, s, 2);
    }
#pragma unroll
    for (int j = 0; j < 2; j++) {
        bool up = lane & 4;
        float s = up ? y[j] : y[j+2];
        float k = up ? y[j+2] : y[j];
        y[j] = k + __shfl_xor_sync(0xffffffffu, s, 4);
    }
    {
        bool up = lane & 8;
        float s = up ? y[0] : y[1];
        float k = up ? y[1] : y[0];
        y[0] = k + __shfl_xor_sync(0xffffffffu, s, 8);
    }
    y[0] += __shfl_xor_sync(0xffffffffu, y[0], 16);
    return y[0];
}

#define CJ(j)  ((((j)&1)<<1) | (((j)>>1)&1))
#define BR3(j) (((((j)&1))<<2) | ((j)&2) | (((j)>>2)&1))

// load wA/wB for one m with 4 LDS.128: wA[q]/wB[q] are the two halves of the
// aligned 16B word at wm+4q; select by L0 (SELs on the idle ALU pipe).
#define LOAD_W(wm)                                            \
    do {                                                      \
        _Pragma("unroll")                                     \
        for (int q = 0; q < 4; q++) {                         \
            ulonglong2 wt = *(const ulonglong2*)((wm) + 4*q); \
            wA[q] = L0 ? wt.y : wt.x;                         \
            wB[q] = L0 ? wt.x : wt.y;                         \
        }                                                     \
    } while (0)

// ======================= the single fused kernel =======================
__global__ __cluster_dims__(4,1,1) __launch_bounds__(THREADS,1)
void k_mega(const float* __restrict__ l, const float* __restrict__ g,
            const float* __restrict__ w, const float* __restrict__ beta_a,
            const float* __restrict__ beta_u, float* __restrict__ out)
{
    __shared__ alignas(16) float w_sh[CPB*160];
    __shared__ alignas(16) float ep_sh[MM*32];   // [m][u][i2lo,i2hi,mu2nlo,mu2nhi]
    __shared__ alignas(16) float Ush[CPB*64];    // per-channel l-statistics (pass A)
    __shared__ float K_sh[10], a_sh[10], Rtot[10];
    __shared__ float acc1[160], acc2[160], accR[16];

    const int tid = threadIdx.x, lane = tid & 31;
    const int crank = blockIdx.x & 3;
    const int n     = blockIdx.x >> 2;

    const int Lp = (lane >> 1) & 3;
    const int L0 = lane & 1;
    const int L7 = lane & 7;

    for (int i = tid; i < CPB*160; i += THREADS)
        w_sh[i] = w[(crank*CPB)*160 + i];
    for (int i = tid; i < CPB*64; i += THREADS)
        Ush[i] = 0.f;
    if (tid < 160) { acc1[tid] = 0.f; acc2[tid] = 0.f; }
    if (tid < 16)  accR[tid] = 0.f;
    __syncthreads();

    float* accp = (((lane>>3)&1) ? acc2 : acc1) + 4*Lp + 2*L0 + ((lane>>4)&1);

    const uint32_t a1addr = smem_u32(&acc1[tid < 160 ? tid : 0]);
    const uint32_t a2addr = smem_u32(&acc2[tid < 160 ? tid : 0]);
    const uint32_t aRaddr = smem_u32(&accR[tid < 16  ? tid : 0]);

    const int em = (tid < 160) ? (tid >> 4) : 0;
    const int ed = tid & 15;
    const float ba = beta_a[em], bu = beta_u[em];

    // ================= PASS A via per-channel l-statistics =================
    // Warp-uniform work mapping: wi = k*16+warp in [0,32) -> channel wi>>2, sub wi&3.
    for (int k = 0; k < 2; k++) {
        const int wi = k*16 + (tid >> 5);
        {
            const int cl = wi >> 2, sub = wi & 3;
            const int pi = sub*32 + lane;        // pair index within channel
            const bool act = pi < (SSZ/2);
            const int s = act ? 2*pi : 0;
            const float* lbase = l + ((size_t)(n*CC + crank*CPB + cl)*16)*SSZ + s;
            float2 lf[16];
#pragma unroll
            for (int i = 0; i < 16; i++) {
                int d = 4*((i>>2) ^ Lp) + ((i&2) ^ (L0<<1)) + (i&1);
                float2 t = *(const float2*)(lbase + d*SSZ);
                lf[i] = act ? t : make_float2(0.f, 0.f);
            }
            float U1s[16], sq[16];
#pragma unroll
            for (int i = 0; i < 16; i++) {
                U1s[i] = lf[i].x + lf[i].y;
                sq[i]  = fmaf(lf[i].x, lf[i].x, lf[i].y*lf[i].y);
            }
            float p01r[4], p23r[4], p02v[4], p13v[4], p03r[4], p12r[4];
#pragma unroll
            for (int gg = 0; gg < 4; gg++) {
                const float2* b = lf + 4*gg;
                p01r[gg] = fmaf(b[0].x, b[1].x, b[0].y*b[1].y);
                p23r[gg] = fmaf(b[2].x, b[3].x, b[2].y*b[3].y);
                p02v[gg] = fmaf(b[0].x, b[2].x, b[0].y*b[2].y);
                p13v[gg] = fmaf(b[1].x, b[3].x, b[1].y*b[3].y);
                p03r[gg] = fmaf(b[0].x, b[3].x, b[0].y*b[3].y);
                p12r[gg] = fmaf(b[1].x, b[2].x, b[1].y*b[2].y);
            }
            u64 y1[8], y1b[8], y2[8], y2b[8];
#pragma unroll
            for (int j = 0; j < 8; j++) {
                const int gg = CJ(j), jj = j >> 2;
                y1 [j] = pk2(U1s[4*gg+2*jj], U1s[4*gg+2*jj+1]);
                y1b[j] = pk2(sq [4*gg+2*jj], sq [4*gg+2*jj+1]);
                u64 k0  = L0 ? pk2(p23r[gg], p01r[gg]) : pk2(p01r[gg], p23r[gg]);
                u64 k1  = pk2(p02v[gg], p13v[gg]);
                u64 k0b = L0 ? pk2(p12r[gg], p03r[gg]) : pk2(p03r[gg], p12r[gg]);
                const int kb = L0 ^ jj;
                y2 [j] = kb ? k1   : k0;
                y2b[j] = kb ? 0ull : k0b;
            }
            const int sidx = ((lane>>3)&1)*16 + 2*(lane&7) + ((lane>>4)&1);
            float r1 = reduce8x2r(y1, y1b, lane);
            atomicAdd(&Ush[cl*64 + sidx], r1);
            float r2 = reduce8x2r(y2, y2b, lane);
            atomicAdd(&Ush[cl*64 + 32 + sidx], r2);
        }
    }
    __syncthreads();

    // ----- contraction: S1/S2 partials for this CTA's 8 channels -----
    if (tid < 160) {
        const int p_ = ed >> 2, r_ = ed & 3;
        float s1 = 0.f, s2 = 0.f;
#pragma unroll
        for (int c = 0; c < CPB; c++) {
            const float* u   = &Ush[c*64];
            const float* wcm = &w_sh[c*160 + em*16];
            float w0 = wcm[r_], w1 = wcm[4+r_], w2 = wcm[8+r_], w3 = wcm[12+r_];
            const float* u1 = u + 4*p_;
            s1 += w0*u1[0] + w1*u1[1] + w2*u1[2] + w3*u1[3];
            const float* dq = u + 16 + 4*p_;
            s2 += w0*w0*dq[0] + w1*w1*dq[1] + w2*w2*dq[2] + w3*w3*dq[3];
            const float* pp = u + 32 + 4*p_;
            float cr = w0*w1*pp[0] + w2*w3*pp[1] + w0*w2*pp[2] + w1*w3*pp[3];
            const float* pv = u + 48 + 4*p_;
            cr += w0*w3*pv[0] + w1*w2*pv[1];
            s2 += 2.f*cr;
        }
        acc1[tid] = s1;
        acc2[tid] = s2;
    }
    __syncthreads();
    cluster_sync_();

    // ----- combine S1/S2 across the 4 CTAs -----
    float S1 = 0.f, S2 = 0.f;
    if (tid < 160) {
#pragma unroll
        for (uint32_t rk = 0; rk < 4; rk++) {
            S1 += cluster_ld_f32(a1addr, rk);
            S2 += cluster_ld_f32(a2addr, rk);
        }
    }
    cluster_sync_();
    if (tid < 160) { acc1[tid] = 0.f; acc2[tid] = 0.f; }

    // ----- epilogue A -----
    if (tid < 160) {
        float gv = g[(n*MM + em)*16 + ed];
        float sig0 = S2 - 2.f*gv*S1 + BBF*gv*gv + EPSF;
        float sl = logf(sig0);
#pragma unroll
        for (int o = 8; o > 0; o >>= 1) sl += __shfl_xor_sync(0xffffffffu, sl, o);

        float a0 = 1.f / (1.f + expf(-(LAM_INIT * (ba - 16.f*bu - 0.5f*sl))));
        float rsum  = BBF * a0 * 0.1f;
        float coeff = (a0 * 0.1f) / (rsum + EPSF);
        float mu    = coeff * S1;
        float sig   = coeff * (S2 - 2.f*mu*S1 + BBF*mu*mu) + EPSF;
        float sl2 = logf(sig);
#pragma unroll
        for (int o = 8; o > 0; o >>= 1) sl2 += __shfl_xor_sync(0xffffffffu, sl2, o);

        float logit = LAM_ROUT * (ba - rsum * (16.f*bu + 0.5f*sl2));
        float a1 = 1.f / (1.f + expf(-logit));

        float i2  = 0.5f / sig;
        float cst = mu*mu*i2;
#pragma unroll
        for (int o = 8; o > 0; o >>= 1) cst += __shfl_xor_sync(0xffffffffu, cst, o);

        ep_sh[em*32 + (ed>>1)*4 +     (ed&1)] = i2;
        ep_sh[em*32 + (ed>>1)*4 + 2 + (ed&1)] = -(mu / sig);
        if (ed == 0) {
            a_sh[em] = a1;
            K_sh[em] = -0.5f*sl2 - 8.f*LN2PI + logf(a1) - cst;
        }
    }
    __syncthreads();

    // ================= routing iterations 1 and 2 =================
    for (int it = 0; it < 2; it++) {
#pragma unroll
        for (int k = 0; k < NITER; k++) {
            // warp-uniform skip of fully-inactive warps (no barriers inside body)
            if ((tid & ~31) + k*THREADS >= NPAIRS) continue;
            const int pr = tid + k*THREADS;
            const bool act = pr < NPAIRS;
            const int prc = act ? pr : 0;
            const int cl = prc / (SSZ/2), s = 2*prc - cl*SSZ;
            const float* lbase = l + ((size_t)(n*CC + crank*CPB + cl)*16)*SSZ + s;
            float2 lf[16];
#pragma unroll
            for (int i = 0; i < 16; i++) {
                int d = 4*((i>>2) ^ Lp) + (i&3);
                float2 t = *(const float2*)(lbase + d*SSZ);
                lf[i] = act ? t : make_float2(0.f, 0.f);
            }

            // ---- E-step: both items ----
            float lnapA[10], lnapB[10];
#pragma unroll
            for (int m = 0; m < MM; m++) {
                const float* wm = &w_sh[cl*160 + m*16];
                u64 wA[4], wB[4];
                LOAD_W(wm);
                u64 qA = 0ull, qB = 0ull;
#pragma unroll
                for (int j = 0; j < 8; j++) {
                    const int cj = CJ(j);
                    const u64* wc = (j < 4) ? wA : wB;
                    const int u = L7 ^ BR3(j);
                    ulonglong2 ep = *(const ulonglong2*)&ep_sh[m*32 + u*4];
                    u64 vA = fma2(bc2(lf[4*cj].x),   wc[0],
                             fma2(bc2(lf[4*cj+1].x), wc[1],
                             fma2(bc2(lf[4*cj+2].x), wc[2],
                             mul2(bc2(lf[4*cj+3].x), wc[3]))));
                    u64 vB = fma2(bc2(lf[4*cj].y),   wc[0],
                             fma2(bc2(lf[4*cj+1].y), wc[1],
                             fma2(bc2(lf[4*cj+2].y), wc[2],
                             mul2(bc2(lf[4*cj+3].y), wc[3]))));
                    qA = fma2(vA, fma2(vA, ep.x, ep.y), qA);
                    qB = fma2(vB, fma2(vB, ep.x, ep.y), qB);
                }
                float ql, qh;
                upk(qA, ql, qh); lnapA[m] = K_sh[m] - (ql + qh);
                upk(qB, ql, qh); lnapB[m] = K_sh[m] - (ql + qh);
            }

            // stable softmax * a, both items; inactive threads masked to 0
            {
                float mxA = lnapA[0], mxB = lnapB[0];
#pragma unroll
                for (int m = 1; m < MM; m++) { mxA = fmaxf(mxA, lnapA[m]); mxB = fmaxf(mxB, lnapB[m]); }
                float dA = 0.f, dB = 0.f;
#pragma unroll
                for (int m = 0; m < MM; m++) {
                    lnapA[m] = __expf(lnapA[m] - mxA); dA += lnapA[m];
                    lnapB[m] = __expf(lnapB[m] - mxB); dB += lnapB[m];
                }
                float sA = act ? (1.f / dA) : 0.f;
                float sB = act ? (1.f / dB) : 0.f;
#pragma unroll
                for (int m = 0; m < MM; m++) {
                    lnapA[m] = lnapA[m] * sA * a_sh[m];
                    lnapB[m] = lnapB[m] * sB * a_sh[m];
                }
            }

            // ---- M-step statistics: pair-accumulated before reduction ----
#pragma unroll
            for (int m = 0; m < MM; m++) {
                const float* wm = &w_sh[cl*160 + m*16];
                u64 wA[4], wB[4];
                LOAD_W(wm);
                u64 rA = bc2(lnapA[m]), rB = bc2(lnapB[m]);
                u64 yV[8], yV2[8];
#pragma unroll
                for (int j = 0; j < 8; j++) {
                    const int cj = CJ(j);
                    const u64* wc = (j < 4) ? wA : wB;
                    u64 vA = fma2(bc2(lf[4*cj].x),   wc[0],
                             fma2(bc2(lf[4*cj+1].x), wc[1],
                             fma2(bc2(lf[4*cj+2].x), wc[2],
                             mul2(bc2(lf[4*cj+3].x), wc[3]))));
                    u64 vB = fma2(bc2(lf[4*cj].y),   wc[0],
                             fma2(bc2(lf[4*cj+1].y), wc[1],
                             fma2(bc2(lf[4*cj+2].y), wc[2],
                             mul2(bc2(lf[4*cj+3].y), wc[3]))));
                    u64 cA = mul2(rA, vA), cB = mul2(rB, vB);
                    yV [j] = add2(cA, cB);
                    yV2[j] = add2(mul2(cA, vA), mul2(cB, vB));
                }
                float res = reduce8x2r(yV, yV2, lane);
                atomicAdd(accp + m*16, res);
            }
            // R sums (pair-summed)
            {
                float y[16];
#pragma unroll
                for (int m = 0; m < MM; m++) y[m] = lnapA[m] + lnapB[m];
#pragma unroll
                for (int m = MM; m < 16; m++) y[m] = 0.f;
                float val = reduce16_to_lane(y, lane);
                int idx4 = bitrev4(lane & 15);
                if (lane < 16 && idx4 < MM) atomicAdd(&accR[idx4], val);
            }
        }
        __syncthreads();
        cluster_sync_();

        // combine A1/A2/R across CTAs
        float A1 = 0.f, A2 = 0.f, R = 0.f;
        if (tid < 160) {
#pragma unroll
            for (uint32_t rk = 0; rk < 4; rk++) {
                A1 += cluster_ld_f32(a1addr, rk);
                A2 += cluster_ld_f32(a2addr, rk);
            }
        }
        if (tid < 16) {
#pragma unroll
            for (uint32_t rk = 0; rk < 4; rk++) R += cluster_ld_f32(aRaddr, rk);
        }
        cluster_sync_();
        if (tid < 160) { acc1[tid] = 0.f; acc2[tid] = 0.f; }
        if (tid < 16)  accR[tid] = 0.f;
        if (tid < 10)  Rtot[tid] = R;
        __syncthreads();

        if (tid < 160) {
            float Rm  = Rtot[em];
            float inv = 1.f / (Rm + EPSF);
            float mu  = A1 * inv;
            float sig = (A2 - 2.f*mu*A1 + mu*mu*Rm) * inv + EPSF;
            float sl  = logf(sig);
#pragma unroll
            for (int o = 8; o > 0; o >>= 1) sl += __shfl_xor_sync(0xffffffffu, sl, o);

            float logit = LAM_ROUT * (ba - Rm * (16.f*bu + 0.5f*sl));
            float a = 1.f / (1.f + expf(-logit));

            if (it == 0) {
                float i2  = 0.5f / sig;
                float cst = mu*mu*i2;
#pragma unroll
                for (int o = 8; o > 0; o >>= 1) cst += __shfl_xor_sync(0xffffffffu, cst, o);
                ep_sh[em*32 + (ed>>1)*4 +     (ed&1)] = i2;
                ep_sh[em*32 + (ed>>1)*4 + 2 + (ed&1)] = -(mu / sig);
                if (ed == 0) {
                    a_sh[em] = a;
                    K_sh[em] = -0.5f*sl - 8.f*LN2PI + logf(a) - cst;
                }
            } else if (crank == 0) {
                out[NN*MM + n*160 + tid] = mu;          // mu block (N, M, 16)
                if (ed == 0) out[n*MM + em] = a;        // a_out block (N, M)
            }
        }
        __syncthreads();
    }
}

extern "C" void kernel_launch(void* const* d_in, const int* in_sizes, int n_in,
                              void* d_out, int out_size)
{
    const float* l      = (const float*)d_in[0];
    const float* g      = (const float*)d_in[1];
    const float* weight = (const float*)d_in[2];
    const float* beta_a = (const float*)d_in[3];
    const float* beta_u = (const float*)d_in[4];
    float* out = (float*)d_out;

    k_mega<<<NN*4, THREADS>>>(l, g, weight, beta_a, beta_u, out);

    (void)in_sizes; (void)n_in; (void)out_size;
}

// round 14
// speedup vs baseline: 1.4504x; 1.0322x over previous
#include <cuda_runtime.h>
#include <math.h>
#include <stdint.h>

#define NN 32
#define CC 32
#define MM 10
#define SSZ 196
#define CPB 8                 // channels per CTA
#define ITEMS (CPB*SSZ)       // 1568 items per CTA
#define NPAIRS (ITEMS/2)      // 784 item-pairs per CTA
#define THREADS 512
#define NITER ((NPAIRS + THREADS - 1) / THREADS)   // 2, uniform for all threads
#define BBF 6272.0f
#define EPSF 1e-6f
#define LAM_INIT 0.001f
#define LAM_ROUT 0.001f
#define LN2PI 1.8378770664093453f

typedef unsigned long long u64;

// ---- packed f32x2 helpers ----
__device__ __forceinline__ u64 pk2(float lo, float hi) {
    u64 r; asm("mov.b64 %0, {%1,%2};" : "=l"(r) : "f"(lo), "f"(hi)); return r;
}
__device__ __forceinline__ u64 bc2(float x) { return pk2(x, x); }
__device__ __forceinline__ void upk(u64 v, float& lo, float& hi) {
    asm("mov.b64 {%0,%1}, %2;" : "=f"(lo), "=f"(hi) : "l"(v));
}
__device__ __forceinline__ u64 fma2(u64 a, u64 b, u64 c) {
    u64 d; asm("fma.rn.f32x2 %0, %1, %2, %3;" : "=l"(d) : "l"(a), "l"(b), "l"(c)); return d;
}
__device__ __forceinline__ u64 mul2(u64 a, u64 b) {
    u64 d; asm("mul.rn.f32x2 %0, %1, %2;" : "=l"(d) : "l"(a), "l"(b)); return d;
}
__device__ __forceinline__ u64 add2(u64 a, u64 b) {
    u64 d; asm("add.rn.f32x2 %0, %1, %2;" : "=l"(d) : "l"(a), "l"(b)); return d;
}
__device__ __forceinline__ u64 shx2(u64 v, int d) {
    return __shfl_xor_sync(0xffffffffu, v, d);
}

// ---- cluster helpers ----
__device__ __forceinline__ void cluster_sync_() {
    asm volatile("barrier.cluster.arrive.aligned;" ::: "memory");
    asm volatile("barrier.cluster.wait.aligned;"   ::: "memory");
}
__device__ __forceinline__ uint32_t smem_u32(const void* p) {
    uint32_t a;
    asm("{ .reg .u64 t; cvta.to.shared.u64 t, %1; cvt.u32.u64 %0, t; }" : "=r"(a) : "l"(p));
    return a;
}
__device__ __forceinline__ float cluster_ld_f32(uint32_t laddr, uint32_t rank) {
    uint32_t ra; float v;
    asm("mapa.shared::cluster.u32 %0, %1, %2;" : "=r"(ra) : "r"(laddr), "r"(rank));
    asm volatile("ld.shared::cluster.f32 %0, [%1];" : "=f"(v) : "r"(ra) : "memory");
    return v;
}

__device__ __forceinline__ int bitrev4(int x) {
    return ((x&1)<<3) | (((x>>1)&1)<<2) | (((x>>2)&1)<<1) | ((x>>3)&1);
}

// SEL-free permuted dual reduction with merged tail (see R11).
// Lane L placed slot (L&7)^bitrev3(j) at position j for both arrays.
// Returns the single scalar this lane owns: array = bit3, slot = lane&7,
// component (lo/hi) = bit4.
__device__ __forceinline__ float reduce8x2r(u64 (&yA)[8], u64 (&yB)[8], int lane)
{
#pragma unroll
    for (int j = 0; j < 4; j++) {
        yA[j] = add2(yA[j], shx2(yA[j+4], 1));
        yB[j] = add2(yB[j], shx2(yB[j+4], 1));
    }
#pragma unroll
    for (int j = 0; j < 2; j++) {
        yA[j] = add2(yA[j], shx2(yA[j+2], 2));
        yB[j] = add2(yB[j], shx2(yB[j+2], 2));
    }
    yA[0] = add2(yA[0], shx2(yA[1], 4));
    yB[0] = add2(yB[0], shx2(yB[1], 4));
    u64 keep = (lane & 8) ? yB[0] : yA[0];
    u64 send = (lane & 8) ? yA[0] : yB[0];
    u64 z = add2(keep, shx2(send, 8));
    float lo, hi; upk(z, lo, hi);
    float kp = (lane & 16) ? hi : lo;
    float sd = (lane & 16) ? lo : hi;
    return kp + __shfl_xor_sync(0xffffffffu, sd, 16);
}

// 16 scalars across 32 lanes (R); lane owns bitrev4(lane&15).
__device__ __forceinline__ float reduce16_to_lane(float (&y)[16], int lane)
{
#pragma unroll
    for (int j = 0; j < 8; j++) {
        bool up = lane & 1;
        float s = up ? y[j] : y[j+8];
        float k = up ? y[j+8] : y[j];
        y[j] = k + __shfl_xor_sync(0xffffffffu, s, 1);
    }
#pragma unroll
    for (int j = 0; j < 4; j++) {
        bool up = lane & 2;
        float s = up ? y[j] : y[j+4];
        float k = up ? y[j+4] : y[j];
        y[j] = k + __shfl_xor_sync(0xffffffffu, s, 2);
    }
#pragma unroll
    for (int j = 0; j < 2; j++) {
        bool up = lane & 4;
        float s = up ? y[j] : y[j+2];
        float k = up ? y[j+2] : y[j];
        y[j] = k + __shfl_xor_sync(0xffffffffu, s, 4);
    }
    {
        bool up = lane & 8;
        float s = up ? y[0] : y[1];
        float k = up ? y[1] : y[0];
        y[0] = k + __shfl_xor_sync(0xffffffffu, s, 8);
    }
    y[0] += __shfl_xor_sync(0xffffffffu, y[0], 16);
    return y[0];
}

#define CJ(j)  ((((j)&1)<<1) | (((j)>>1)&1))
#define BR3(j) (((((j)&1))<<2) | ((j)&2) | (((j)>>2)&1))

// ======================= the single fused kernel =======================
__global__ __cluster_dims__(4,1,1) __launch_bounds__(THREADS,1)
void k_mega(const float* __restrict__ l, const float* __restrict__ g,
            const float* __restrict__ w, const float* __restrict__ beta_a,
            const float* __restrict__ beta_u, float* __restrict__ out)
{
    __shared__ alignas(16) float w_sh[CPB*160];
    __shared__ alignas(16) float ep_sh[MM*32];   // [m][u][i2lo,i2hi,mu2nlo,mu2nhi]
    __shared__ alignas(16) float Ush[CPB*64];    // per-channel l-statistics (pass A)
    __shared__ float K_sh[10], a_sh[10], Rtot[10];
    __shared__ float acc1[160], acc2[160], accR[16];

    const int tid = threadIdx.x, lane = tid & 31;
    const int crank = blockIdx.x & 3;
    const int n     = blockIdx.x >> 2;

    const int Lp = (lane >> 1) & 3;
    const int L0 = lane & 1;
    const int L7 = lane & 7;

    for (int i = tid; i < CPB*160; i += THREADS)
        w_sh[i] = w[(crank*CPB)*160 + i];
    for (int i = tid; i < CPB*64; i += THREADS)
        Ush[i] = 0.f;
    if (tid < 160) { acc1[tid] = 0.f; acc2[tid] = 0.f; }
    if (tid < 16)  accR[tid] = 0.f;
    __syncthreads();

    float* accp = (((lane>>3)&1) ? acc2 : acc1) + 4*Lp + 2*L0 + ((lane>>4)&1);

    const uint32_t a1addr = smem_u32(&acc1[tid < 160 ? tid : 0]);
    const uint32_t a2addr = smem_u32(&acc2[tid < 160 ? tid : 0]);
    const uint32_t aRaddr = smem_u32(&accR[tid < 16  ? tid : 0]);

    const int em = (tid < 160) ? (tid >> 4) : 0;
    const int ed = tid & 15;
    const float ba = beta_a[em], bu = beta_u[em];

    // ================= PASS A via per-channel l-statistics =================
    // Warp-uniform work mapping: wi = k*16+warp in [0,32) -> channel wi>>2, sub wi&3.
    for (int k = 0; k < 2; k++) {
        const int wi = k*16 + (tid >> 5);
        {
            const int cl = wi >> 2, sub = wi & 3;
            const int pi = sub*32 + lane;        // pair index within channel
            const bool act = pi < (SSZ/2);
            const int s = act ? 2*pi : 0;
            const float* lbase = l + ((size_t)(n*CC + crank*CPB + cl)*16)*SSZ + s;
            float2 lf[16];
#pragma unroll
            for (int i = 0; i < 16; i++) {
                int d = 4*((i>>2) ^ Lp) + ((i&2) ^ (L0<<1)) + (i&1);
                float2 t = *(const float2*)(lbase + d*SSZ);
                lf[i] = act ? t : make_float2(0.f, 0.f);
            }
            float U1s[16], sq[16];
#pragma unroll
            for (int i = 0; i < 16; i++) {
                U1s[i] = lf[i].x + lf[i].y;
                sq[i]  = fmaf(lf[i].x, lf[i].x, lf[i].y*lf[i].y);
            }
            float p01r[4], p23r[4], p02v[4], p13v[4], p03r[4], p12r[4];
#pragma unroll
            for (int gg = 0; gg < 4; gg++) {
                const float2* b = lf + 4*gg;
                p01r[gg] = fmaf(b[0].x, b[1].x, b[0].y*b[1].y);
                p23r[gg] = fmaf(b[2].x, b[3].x, b[2].y*b[3].y);
                p02v[gg] = fmaf(b[0].x, b[2].x, b[0].y*b[2].y);
                p13v[gg] = fmaf(b[1].x, b[3].x, b[1].y*b[3].y);
                p03r[gg] = fmaf(b[0].x, b[3].x, b[0].y*b[3].y);
                p12r[gg] = fmaf(b[1].x, b[2].x, b[1].y*b[2].y);
            }
            u64 y1[8], y1b[8], y2[8], y2b[8];
#pragma unroll
            for (int j = 0; j < 8; j++) {
                const int gg = CJ(j), jj = j >> 2;
                y1 [j] = pk2(U1s[4*gg+2*jj], U1s[4*gg+2*jj+1]);
                y1b[j] = pk2(sq [4*gg+2*jj], sq [4*gg+2*jj+1]);
                u64 k0  = L0 ? pk2(p23r[gg], p01r[gg]) : pk2(p01r[gg], p23r[gg]);
                u64 k1  = pk2(p02v[gg], p13v[gg]);
                u64 k0b = L0 ? pk2(p12r[gg], p03r[gg]) : pk2(p03r[gg], p12r[gg]);
                const int kb = L0 ^ jj;
                y2 [j] = kb ? k1   : k0;
                y2b[j] = kb ? 0ull : k0b;
            }
            const int sidx = ((lane>>3)&1)*16 + 2*(lane&7) + ((lane>>4)&1);
            float r1 = reduce8x2r(y1, y1b, lane);
            atomicAdd(&Ush[cl*64 + sidx], r1);
            float r2 = reduce8x2r(y2, y2b, lane);
            atomicAdd(&Ush[cl*64 + 32 + sidx], r2);
        }
    }
    __syncthreads();

    // ----- contraction: S1/S2 partials for this CTA's 8 channels -----
    if (tid < 160) {
        const int p_ = ed >> 2, r_ = ed & 3;
        float s1 = 0.f, s2 = 0.f;
#pragma unroll
        for (int c = 0; c < CPB; c++) {
            const float* u   = &Ush[c*64];
            const float* wcm = &w_sh[c*160 + em*16];
            float w0 = wcm[r_], w1 = wcm[4+r_], w2 = wcm[8+r_], w3 = wcm[12+r_];
            const float* u1 = u + 4*p_;
            s1 += w0*u1[0] + w1*u1[1] + w2*u1[2] + w3*u1[3];
            const float* dq = u + 16 + 4*p_;
            s2 += w0*w0*dq[0] + w1*w1*dq[1] + w2*w2*dq[2] + w3*w3*dq[3];
            const float* pp = u + 32 + 4*p_;
            float cr = w0*w1*pp[0] + w2*w3*pp[1] + w0*w2*pp[2] + w1*w3*pp[3];
            const float* pv = u + 48 + 4*p_;
            cr += w0*w3*pv[0] + w1*w2*pv[1];
            s2 += 2.f*cr;
        }
        acc1[tid] = s1;
        acc2[tid] = s2;
    }
    __syncthreads();
    cluster_sync_();

    // ----- combine S1/S2 across the 4 CTAs -----
    float S1 = 0.f, S2 = 0.f;
    if (tid < 160) {
#pragma unroll
        for (uint32_t rk = 0; rk < 4; rk++) {
            S1 += cluster_ld_f32(a1addr, rk);
            S2 += cluster_ld_f32(a2addr, rk);
        }
    }
    cluster_sync_();
    if (tid < 160) { acc1[tid] = 0.f; acc2[tid] = 0.f; }

    // ----- epilogue A -----
    if (tid < 160) {
        float gv = g[(n*MM + em)*16 + ed];
        float sig0 = S2 - 2.f*gv*S1 + BBF*gv*gv + EPSF;
        float sl = logf(sig0);
#pragma unroll
        for (int o = 8; o > 0; o >>= 1) sl += __shfl_xor_sync(0xffffffffu, sl, o);

        float a0 = 1.f / (1.f + expf(-(LAM_INIT * (ba - 16.f*bu - 0.5f*sl))));
        float rsum  = BBF * a0 * 0.1f;
        float coeff = (a0 * 0.1f) / (rsum + EPSF);
        float mu    = coeff * S1;
        float sig   = coeff * (S2 - 2.f*mu*S1 + BBF*mu*mu) + EPSF;
        float sl2 = logf(sig);
#pragma unroll
        for (int o = 8; o > 0; o >>= 1) sl2 += __shfl_xor_sync(0xffffffffu, sl2, o);

        float logit = LAM_ROUT * (ba - rsum * (16.f*bu + 0.5f*sl2));
        float a1 = 1.f / (1.f + expf(-logit));

        float i2  = 0.5f / sig;
        float cst = mu*mu*i2;
#pragma unroll
        for (int o = 8; o > 0; o >>= 1) cst += __shfl_xor_sync(0xffffffffu, cst, o);

        ep_sh[em*32 + (ed>>1)*4 +     (ed&1)] = i2;
        ep_sh[em*32 + (ed>>1)*4 + 2 + (ed&1)] = -(mu / sig);
        if (ed == 0) {
            a_sh[em] = a1;
            K_sh[em] = -0.5f*sl2 - 8.f*LN2PI + logf(a1) - cst;
        }
    }
    __syncthreads();

    // ================= routing iterations 1 and 2 =================
    for (int it = 0; it < 2; it++) {
#pragma unroll
        for (int k = 0; k < NITER; k++) {
            // warp-uniform skip of fully-inactive warps (no barriers inside body)
            if ((tid & ~31) + k*THREADS >= NPAIRS) continue;
            const int pr = tid + k*THREADS;
            const bool act = pr < NPAIRS;
            const int prc = act ? pr : 0;
            const int cl = prc / (SSZ/2), s = 2*prc - cl*SSZ;
            const float* lbase = l + ((size_t)(n*CC + crank*CPB + cl)*16)*SSZ + s;
            float2 lf[16];
#pragma unroll
            for (int i = 0; i < 16; i++) {
                int d = 4*((i>>2) ^ Lp) + (i&3);
                float2 t = *(const float2*)(lbase + d*SSZ);
                lf[i] = act ? t : make_float2(0.f, 0.f);
            }

            // ---- E-step: both items ----
            float lnapA[10], lnapB[10];
#pragma unroll
            for (int m = 0; m < MM; m++) {
                const float* wm = &w_sh[cl*160 + m*16];
                u64 wA[4], wB[4];
#pragma unroll
                for (int q = 0; q < 4; q++) {
                    wA[q] = *(const u64*)(wm + 4*q + 2*L0);
                    wB[q] = *(const u64*)(wm + 4*q + 2*(L0^1));
                }
                u64 qA = 0ull, qB = 0ull;
#pragma unroll
                for (int j = 0; j < 8; j++) {
                    const int cj = CJ(j);
                    const u64* wc = (j < 4) ? wA : wB;
                    const int u = L7 ^ BR3(j);
                    ulonglong2 ep = *(const ulonglong2*)&ep_sh[m*32 + u*4];
                    u64 vA = fma2(bc2(lf[4*cj].x),   wc[0],
                             fma2(bc2(lf[4*cj+1].x), wc[1],
                             fma2(bc2(lf[4*cj+2].x), wc[2],
                             mul2(bc2(lf[4*cj+3].x), wc[3]))));
                    u64 vB = fma2(bc2(lf[4*cj].y),   wc[0],
                             fma2(bc2(lf[4*cj+1].y), wc[1],
                             fma2(bc2(lf[4*cj+2].y), wc[2],
                             mul2(bc2(lf[4*cj+3].y), wc[3]))));
                    qA = fma2(vA, fma2(vA, ep.x, ep.y), qA);
                    qB = fma2(vB, fma2(vB, ep.x, ep.y), qB);
                }
                float ql, qh;
                upk(qA, ql, qh); lnapA[m] = K_sh[m] - (ql + qh);
                upk(qB, ql, qh); lnapB[m] = K_sh[m] - (ql + qh);
            }

            // stable softmax * a, both items; inactive threads masked to 0
            {
                float mxA = lnapA[0], mxB = lnapB[0];
#pragma unroll
                for (int m = 1; m < MM; m++) { mxA = fmaxf(mxA, lnapA[m]); mxB = fmaxf(mxB, lnapB[m]); }
                float dA = 0.f, dB = 0.f;
#pragma unroll
                for (int m = 0; m < MM; m++) {
                    lnapA[m] = __expf(lnapA[m] - mxA); dA += lnapA[m];
                    lnapB[m] = __expf(lnapB[m] - mxB); dB += lnapB[m];
                }
                float sA = act ? (1.f / dA) : 0.f;
                float sB = act ? (1.f / dB) : 0.f;
#pragma unroll
                for (int m = 0; m < MM; m++) {
                    lnapA[m] = lnapA[m] * sA * a_sh[m];
                    lnapB[m] = lnapB[m] * sB * a_sh[m];
                }
            }

            // ---- R sums first: its shuffle chain drains under the M-loop math ----
            {
                float y[16];
#pragma unroll
                for (int m = 0; m < MM; m++) y[m] = lnapA[m] + lnapB[m];
#pragma unroll
                for (int m = MM; m < 16; m++) y[m] = 0.f;
                float val = reduce16_to_lane(y, lane);
                int idx4 = bitrev4(lane & 15);
                if (lane < 16 && idx4 < MM) atomicAdd(&accR[idx4], val);
            }

            // ---- M-step statistics: pair-accumulated before reduction ----
#pragma unroll
            for (int m = 0; m < MM; m++) {
                const float* wm = &w_sh[cl*160 + m*16];
                u64 wA[4], wB[4];
#pragma unroll
                for (int q = 0; q < 4; q++) {
                    wA[q] = *(const u64*)(wm + 4*q + 2*L0);
                    wB[q] = *(const u64*)(wm + 4*q + 2*(L0^1));
                }
                u64 rA = bc2(lnapA[m]), rB = bc2(lnapB[m]);
                u64 yV[8], yV2[8];
#pragma unroll
                for (int j = 0; j < 8; j++) {
                    const int cj = CJ(j);
                    const u64* wc = (j < 4) ? wA : wB;
                    u64 vA = fma2(bc2(lf[4*cj].x),   wc[0],
                             fma2(bc2(lf[4*cj+1].x), wc[1],
                             fma2(bc2(lf[4*cj+2].x), wc[2],
                             mul2(bc2(lf[4*cj+3].x), wc[3]))));
                    u64 vB = fma2(bc2(lf[4*cj].y),   wc[0],
                             fma2(bc2(lf[4*cj+1].y), wc[1],
                             fma2(bc2(lf[4*cj+2].y), wc[2],
                             mul2(bc2(lf[4*cj+3].y), wc[3]))));
                    u64 cA = mul2(rA, vA), cB = mul2(rB, vB);
                    yV [j] = add2(cA, cB);
                    yV2[j] = add2(mul2(cA, vA), mul2(cB, vB));
                }
                float res = reduce8x2r(yV, yV2, lane);
                atomicAdd(accp + m*16, res);
            }
        }
        __syncthreads();
        cluster_sync_();

        // combine A1/A2/R across CTAs
        float A1 = 0.f, A2 = 0.f, R = 0.f;
        if (tid < 160) {
#pragma unroll
            for (uint32_t rk = 0; rk < 4; rk++) {
                A1 += cluster_ld_f32(a1addr, rk);
                A2 += cluster_ld_f32(a2addr, rk);
            }
        }
        if (tid < 16) {
#pragma unroll
            for (uint32_t rk = 0; rk < 4; rk++) R += cluster_ld_f32(aRaddr, rk);
        }
        cluster_sync_();
        if (tid < 160) { acc1[tid] = 0.f; acc2[tid] = 0.f; }
        if (tid < 16)  accR[tid] = 0.f;
        if (tid < 10)  Rtot[tid] = R;
        __syncthreads();

        if (tid < 160) {
            float Rm  = Rtot[em];
            float inv = 1.f / (Rm + EPSF);
            float mu  = A1 * inv;
            float sig = (A2 - 2.f*mu*A1 + mu*mu*Rm) * inv + EPSF;
            float sl  = logf(sig);
#pragma unroll
            for (int o = 8; o > 0; o >>= 1) sl += __shfl_xor_sync(0xffffffffu, sl, o);

            float logit = LAM_ROUT * (ba - Rm * (16.f*bu + 0.5f*sl));
            float a = 1.f / (1.f + expf(-logit));

            if (it == 0) {
                float i2  = 0.5f / sig;
                float cst = mu*mu*i2;
#pragma unroll
                for (int o = 8; o > 0; o >>= 1) cst += __shfl_xor_sync(0xffffffffu, cst, o);
                ep_sh[em*32 + (ed>>1)*4 +     (ed&1)] = i2;
                ep_sh[em*32 + (ed>>1)*4 + 2 + (ed&1)] = -(mu / sig);
                if (ed == 0) {
                    a_sh[em] = a;
                    K_sh[em] = -0.5f*sl - 8.f*LN2PI + logf(a) - cst;
                }
            } else if (crank == 0) {
                out[NN*MM + n*160 + tid] = mu;          // mu block (N, M, 16)
                if (ed == 0) out[n*MM + em] = a;        // a_out block (N, M)
            }
        }
        __syncthreads();
    }
}

extern "C" void kernel_launch(void* const* d_in, const int* in_sizes, int n_in,
                              void* d_out, int out_size)
{
    const float* l      = (const float*)d_in[0];
    const float* g      = (const float*)d_in[1];
    const float* weight = (const float*)d_in[2];
    const float* beta_a = (const float*)d_in[3];
    const float* beta_u = (const float*)d_in[4];
    float* out = (float*)d_out;

    k_mega<<<NN*4, THREADS>>>(l, g, weight, beta_a, beta_u, out);

    (void)in_sizes; (void)n_in; (void)out_size;
}